// round 1
// baseline (speedup 1.0000x reference)
#include <cuda_runtime.h>
#include <math.h>

// Problem constants
#define NNODES  8192
#define KEDGE   16
#define DDIM    64
#define SDIM    8
#define BDIM    64
#define HHEAD   4
#define FDIM    576     // D*(1+S)
#define FPH     144     // F / H
#define HIDDIM  64

// Kernel tiling
#define GN      8       // nodes per block
#define EPB     128     // edges per block (GN*KEDGE)
#define THREADS 256
#define HST     65      // padded row stride for 128x64 smem tiles (bank spread)

// smem layout (float offsets)
#define OFF_XS  0
#define OFF_A   (OFF_XS + EPB*HST)          // 8320
#define OFF_B   (OFF_A + EPB*HST)
#define OFF_M   (OFF_B + EPB*HST)
#define OFF_W   (OFF_M + EPB*HST)           // 33280 (16B aligned in bytes)
#define OFF_Q   (OFF_W + 64*64)             // 37376
#define OFF_SH  (OFF_Q + GN*64)             // 37888
#define OFF_WL  (OFF_SH + EPB*SDIM)         // 38912
#define OFF_LOG (OFF_WL + 128*4)            // 39424
#define OFF_AL  (OFF_LOG + EPB*4)           // 39936
#define OFF_CUT (OFF_AL + EPB*4)            // 40448
#define OFF_SRC (OFF_CUT + EPB)             // 40576 (ints)
#define SMEM_FLOATS (OFF_SRC + EPB)         // 40704 floats = 162816 B

__device__ __forceinline__ unsigned long long pack2(float x, float y) {
    unsigned long long r;
    asm("mov.b64 %0, {%1, %2};" : "=l"(r) : "f"(x), "f"(y));
    return r;
}
__device__ __forceinline__ void fma2(unsigned long long& d, unsigned long long a, unsigned long long b) {
    asm("fma.rn.f32x2 %0, %1, %2, %0;" : "+l"(d) : "l"(a), "l"(b));
}
__device__ __forceinline__ float2 unpack2(unsigned long long v) {
    float lo, hi;
    asm("mov.b64 {%0, %1}, %2;" : "=f"(lo), "=f"(hi) : "l"(v));
    return make_float2(lo, hi);
}

// jax.nn.gelu default (approximate=True): 0.5*x*(1+tanh(sqrt(2/pi)*(x+0.044715 x^3)))
__device__ __forceinline__ float gelu_f(float x) {
    float x3 = x * x * x;
    float t = tanhf(0.7978845608028654f * (x + 0.044715f * x3));
    return 0.5f * x * (1.0f + t);
}

// 128x64 = [128x64] @ [64x64] GEMM, all operands in smem.
// S: src activations (row stride HST), W: weights (row stride 64, 16B aligned),
// Dst: row stride HST. 256 threads: 4-edge x 8-col register tile each.
template <bool DOGELU>
__device__ __forceinline__ void gemm_tile(const float* S, const float* W, float* Dst) {
    const int tid = threadIdx.x;
    const int j0 = (tid & 7) << 3;   // 0..56
    const int e0 = (tid >> 3) << 2;  // 0..124
    unsigned long long acc[4][4];
#pragma unroll
    for (int i = 0; i < 4; i++)
#pragma unroll
        for (int k = 0; k < 4; k++) acc[i][k] = 0ull;

    const float* s = S + e0 * HST;
    const float* wp = W + j0;
#pragma unroll 8
    for (int b = 0; b < 64; b++) {
        float a0 = s[b];
        float a1 = s[HST + b];
        float a2 = s[2 * HST + b];
        float a3 = s[3 * HST + b];
        ulonglong2 w0 = *reinterpret_cast<const ulonglong2*>(wp + (b << 6));
        ulonglong2 w1 = *reinterpret_cast<const ulonglong2*>(wp + (b << 6) + 4);
        unsigned long long aa0 = pack2(a0, a0);
        unsigned long long aa1 = pack2(a1, a1);
        unsigned long long aa2 = pack2(a2, a2);
        unsigned long long aa3 = pack2(a3, a3);
        fma2(acc[0][0], aa0, w0.x); fma2(acc[0][1], aa0, w0.y);
        fma2(acc[0][2], aa0, w1.x); fma2(acc[0][3], aa0, w1.y);
        fma2(acc[1][0], aa1, w0.x); fma2(acc[1][1], aa1, w0.y);
        fma2(acc[1][2], aa1, w1.x); fma2(acc[1][3], aa1, w1.y);
        fma2(acc[2][0], aa2, w0.x); fma2(acc[2][1], aa2, w0.y);
        fma2(acc[2][2], aa2, w1.x); fma2(acc[2][3], aa2, w1.y);
        fma2(acc[3][0], aa3, w0.x); fma2(acc[3][1], aa3, w0.y);
        fma2(acc[3][2], aa3, w1.x); fma2(acc[3][3], aa3, w1.y);
    }
#pragma unroll
    for (int i = 0; i < 4; i++) {
        float* drow = Dst + (e0 + i) * HST + j0;
#pragma unroll
        for (int k = 0; k < 4; k++) {
            float2 v = unpack2(acc[i][k]);
            if (DOGELU) { v.x = gelu_f(v.x); v.y = gelu_f(v.y); }
            drow[2 * k]     = v.x;
            drow[2 * k + 1] = v.y;
        }
    }
}

__global__ __launch_bounds__(THREADS, 1)
void fused_attn_kernel(const float* __restrict__ node_feat,
                       const float* __restrict__ edge_sh,
                       const float* __restrict__ edge_inv,
                       const float* __restrict__ cutoff,
                       const float* __restrict__ Wk1, const float* __restrict__ Wk2,
                       const float* __restrict__ Wk3,
                       const float* __restrict__ Wv1, const float* __restrict__ Wv2,
                       const float* __restrict__ Wv3,
                       const float* __restrict__ W_logit,
                       const float* __restrict__ W_out,
                       const int* __restrict__ edge_src,
                       float* __restrict__ out) {
    extern __shared__ float sm[];
    const int tid = threadIdx.x;
    const int n0 = blockIdx.x * GN;
    const int e0 = blockIdx.x * EPB;

    float* xs   = sm + OFF_XS;   // x_src [128][64], stride HST
    float* bufA = sm + OFF_A;    // inv -> h2
    float* bufB = sm + OFF_B;    // h1 (key/value), then value acc [8][576]
    float* mbuf = sm + OFF_M;    // gemm3 chunk out [128][64]
    float* Wst  = sm + OFF_W;    // staged weight [64][64]
    float* qn   = sm + OFF_Q;    // [8][64]
    float* shm  = sm + OFF_SH;   // [128][8]
    float* WLs  = sm + OFF_WL;   // [128][4]
    float* lg   = sm + OFF_LOG;  // [128][4]
    float* al   = sm + OFF_AL;   // [128][4] sqrt(alpha)
    float* cw   = sm + OFF_CUT;  // [128]
    int*   srcs = (int*)(sm + OFF_SRC);

    // ---------- phase 0: loads ----------
    if (tid < EPB) {
        srcs[tid] = edge_src[e0 + tid];
        cw[tid]   = cutoff[e0 + tid];
    }
    for (int i = tid; i < GN * 64; i += THREADS) qn[i] = node_feat[n0 * 64 + i];
    for (int i = tid; i < EPB * SDIM; i += THREADS) shm[i] = edge_sh[e0 * SDIM + i];
    for (int i = tid; i < 512; i += THREADS) WLs[i] = W_logit[i];
    for (int i = tid; i < EPB * 4; i += THREADS) lg[i] = 0.0f;
    for (int i = tid; i < EPB * 64; i += THREADS) {
        int e = i >> 6, c = i & 63;
        bufA[e * HST + c] = edge_inv[e0 * 64 + i];
    }
    __syncthreads();  // srcs ready
    for (int i = tid; i < EPB * 64; i += THREADS) {
        int e = i >> 6, c = i & 63;
        xs[e * HST + c] = node_feat[srcs[e] * 64 + c];
    }
    // stage Wk1
    for (int i = tid; i < 4096; i += THREADS) Wst[i] = Wk1[i];
    __syncthreads();

    // ---------- key MLP: h1 = gelu(inv @ Wk1), h2 = gelu(h1 @ Wk2) ----------
    gemm_tile<true>(bufA, Wst, bufB);
    __syncthreads();
    for (int i = tid; i < 4096; i += THREADS) Wst[i] = Wk2[i];
    __syncthreads();
    gemm_tile<true>(bufB, Wst, bufA);
    __syncthreads();

    // ---------- key gemm3 chunks fused into logits ----------
    const int e_f = tid >> 1;          // edge owned for logit fold
    const int tb  = (tid & 1) * 32;    // half of the 64-col chunk
    const float* qrow = qn + (e_f >> 4) * 64;
    float pl0 = 0.f, pl1 = 0.f, pl2 = 0.f, pl3 = 0.f;

    for (int ci = 0; ci < 9; ci++) {
        for (int i = tid; i < 4096; i += THREADS)
            Wst[i] = Wk3[(i >> 6) * FDIM + ci * 64 + (i & 63)];
        __syncthreads();
        gemm_tile<false>(bufA, Wst, mbuf);
        __syncthreads();
        if (ci == 0) {
#pragma unroll 8
            for (int t = tb; t < tb + 32; t++) {
                float m = mbuf[e_f * HST + t];
                float cm = qrow[t] * xs[e_f * HST + t] * m;
                pl0 += cm * WLs[t * 4 + 0];
                pl1 += cm * WLs[t * 4 + 1];
                pl2 += cm * WLs[t * 4 + 2];
                pl3 += cm * WLs[t * 4 + 3];
            }
        } else {
            int dbase = 8 * (ci - 1);
#pragma unroll 8
            for (int t = tb; t < tb + 32; t++) {
                int d = dbase + (t >> 3);
                int s = t & 7;
                float sv = shm[e_f * SDIM + s];
                float m = mbuf[e_f * HST + t];
                float cm = qrow[d] * xs[e_f * HST + d] * sv * sv * m;
                int r = 64 + d;
                pl0 += cm * WLs[r * 4 + 0];
                pl1 += cm * WLs[r * 4 + 1];
                pl2 += cm * WLs[r * 4 + 2];
                pl3 += cm * WLs[r * 4 + 3];
            }
        }
        __syncthreads();
    }
    atomicAdd(&lg[e_f * 4 + 0], pl0);
    atomicAdd(&lg[e_f * 4 + 1], pl1);
    atomicAdd(&lg[e_f * 4 + 2], pl2);
    atomicAdd(&lg[e_f * 4 + 3], pl3);
    __syncthreads();

    // ---------- softmax per (node, head), contiguous 16-edge segments ----------
    if (tid < GN * HHEAD) {
        int n = tid >> 2, h = tid & 3;
        float mx = -3.0e38f;
        for (int j = 0; j < KEDGE; j++)
            mx = fmaxf(mx, lg[(n * KEDGE + j) * 4 + h]);
        float z = 0.f;
        for (int j = 0; j < KEDGE; j++) {
            int e = n * KEDGE + j;
            float ex = cw[e] * expf(lg[e * 4 + h] - mx);
            al[e * 4 + h] = ex;
            z += ex;
        }
        if (z == 0.f) z = 1.f;
        float inv = 1.f / z;
        for (int j = 0; j < KEDGE; j++) {
            int e = n * KEDGE + j;
            al[e * 4 + h] = sqrtf(al[e * 4 + h] * inv);  // sqrt(relu(alpha))
        }
    }
    __syncthreads();

    // ---------- value MLP (reload edge_inv; h2 key in bufA is dead) ----------
    for (int i = tid; i < EPB * 64; i += THREADS) {
        int e = i >> 6, c = i & 63;
        bufA[e * HST + c] = edge_inv[e0 * 64 + i];
    }
    for (int i = tid; i < 4096; i += THREADS) Wst[i] = Wv1[i];
    __syncthreads();
    gemm_tile<true>(bufA, Wst, bufB);
    __syncthreads();
    for (int i = tid; i < 4096; i += THREADS) Wst[i] = Wv2[i];
    __syncthreads();
    gemm_tile<true>(bufB, Wst, bufA);
    __syncthreads();

    float* acc = bufB;  // [8][576] node accumulators (bufB is free now)

    for (int ci = 0; ci < 9; ci++) {
        for (int i = tid; i < 4096; i += THREADS)
            Wst[i] = Wv3[(i >> 6) * FDIM + ci * 64 + (i & 63)];
        __syncthreads();
        gemm_tile<false>(bufA, Wst, mbuf);
        __syncthreads();
        // fold chunk into per-node acc, scaled by out1 * sqrt(alpha[head])
#pragma unroll
        for (int pass = 0; pass < 2; pass++) {
            int idx = tid + pass * THREADS;   // 512 tasks: (node, t)
            int n = idx >> 6, t = idx & 63;
            int c = ci * 64 + t;
            int head = c / FPH;
            float sum = 0.f;
            if (ci == 0) {
#pragma unroll
                for (int j = 0; j < KEDGE; j++) {
                    int e = n * KEDGE + j;
                    sum += xs[e * HST + t] * mbuf[e * HST + t] * al[e * 4 + head];
                }
            } else {
                int d = 8 * (ci - 1) + (t >> 3);
                int s = t & 7;
#pragma unroll
                for (int j = 0; j < KEDGE; j++) {
                    int e = n * KEDGE + j;
                    sum += xs[e * HST + d] * shm[e * SDIM + s] *
                           mbuf[e * HST + t] * al[e * 4 + head];
                }
            }
            acc[n * FDIM + c] = sum;
        }
        __syncthreads();
    }

    // ---------- epilogue: out[n] = acc[n] @ W_out (576x64) ----------
    {
        int dcol = tid & 63;
        int g = tid >> 6;  // 0..3 -> nodes g and g+4
        float s0 = 0.f, s1 = 0.f;
#pragma unroll 8
        for (int c = 0; c < FDIM; c++) {
            float w = W_out[c * 64 + dcol];
            s0 += acc[g * FDIM + c] * w;
            s1 += acc[(g + 4) * FDIM + c] * w;
        }
        out[(n0 + g) * 64 + dcol]     = s0;
        out[(n0 + g + 4) * 64 + dcol] = s1;
    }
}

extern "C" void kernel_launch(void* const* d_in, const int* in_sizes, int n_in,
                              void* d_out, int out_size) {
    const float* node_feat = (const float*)d_in[0];
    const float* edge_sh   = (const float*)d_in[1];
    const float* edge_inv  = (const float*)d_in[2];
    const float* cutoff    = (const float*)d_in[3];
    const float* Wk1       = (const float*)d_in[4];
    const float* Wk2       = (const float*)d_in[5];
    const float* Wk3       = (const float*)d_in[6];
    const float* Wv1       = (const float*)d_in[7];
    const float* Wv2       = (const float*)d_in[8];
    const float* Wv3       = (const float*)d_in[9];
    const float* W_logit   = (const float*)d_in[10];
    const float* W_out     = (const float*)d_in[11];
    const int*   edge_src  = (const int*)d_in[12];
    // d_in[13] = edge_dst: structurally repeat(arange(N), K); implicit in indexing.
    float* out = (float*)d_out;

    size_t smem = SMEM_FLOATS * sizeof(float);
    cudaFuncSetAttribute(fused_attn_kernel,
                         cudaFuncAttributeMaxDynamicSharedMemorySize, (int)smem);
    fused_attn_kernel<<<NNODES / GN, THREADS, smem>>>(
        node_feat, edge_sh, edge_inv, cutoff,
        Wk1, Wk2, Wk3, Wv1, Wv2, Wv3,
        W_logit, W_out, edge_src, out);
}

// round 2
// speedup vs baseline: 1.1318x; 1.1318x over previous
#include <cuda_runtime.h>
#include <math.h>

// Problem constants
#define NNODES  8192
#define KEDGE   16
#define DDIM    64
#define SDIM    8
#define HHEAD   4
#define FDIM    576     // D*(1+S)
#define FPH     144     // F / H

// Tiling: 4 nodes (64 edges) per block, 128 threads, 3 CTAs/SM
#define GN      4
#define EPB     64
#define THREADS 128
#define HST     65      // padded row stride (bank spread)

// smem layout (float offsets)
#define OFF_XS  0                       // [64][65]
#define OFF_A   (OFF_XS + EPB*HST)      // 4160
#define OFF_B   (OFF_A + EPB*HST)       // 8320  (later: node acc [4][576])
#define OFF_W   (OFF_B + EPB*HST)       // 12480 (16B aligned)
#define OFF_Q   (OFF_W + 64*64)         // 16576 [4][64]
#define OFF_SH  (OFF_Q + GN*64)         // 16832 [64][8]
#define OFF_WL  (OFF_SH + EPB*SDIM)     // 17344 [128][4]
#define OFF_LOG (OFF_WL + 128*4)        // 17856 [64][4]
#define OFF_AL  (OFF_LOG + EPB*4)       // 18112 [64][4]
#define OFF_CUT (OFF_AL + EPB*4)        // 18368 [64]
#define OFF_SRC (OFF_CUT + EPB)         // 18432 [64] ints
#define SMEM_FLOATS (OFF_SRC + EPB)     // 18496 floats = 73984 B

__device__ __forceinline__ unsigned long long pack2(float x, float y) {
    unsigned long long r;
    asm("mov.b64 %0, {%1, %2};" : "=l"(r) : "f"(x), "f"(y));
    return r;
}
__device__ __forceinline__ void fma2(unsigned long long& d, unsigned long long a, unsigned long long b) {
    asm("fma.rn.f32x2 %0, %1, %2, %0;" : "+l"(d) : "l"(a), "l"(b));
}
__device__ __forceinline__ float2 unpack2(unsigned long long v) {
    float lo, hi;
    asm("mov.b64 {%0, %1}, %2;" : "=f"(lo), "=f"(hi) : "l"(v));
    return make_float2(lo, hi);
}

__device__ __forceinline__ float gelu_f(float x) {
    float x3 = x * x * x;
    float t = tanhf(0.7978845608028654f * (x + 0.044715f * x3));
    return 0.5f * x * (1.0f + t);
}

// Prefetch a 64x64 weight tile into registers (8 x float4 per thread).
__device__ __forceinline__ void prefetch_w(float4 pf[8], const float* __restrict__ W,
                                           int rowStride, int colOff, int tid) {
#pragma unroll
    for (int k = 0; k < 8; k++) {
        int idx4 = tid + k * THREADS;      // 0..1023
        int row  = idx4 >> 4;              // 0..63
        int c4   = idx4 & 15;
        pf[k] = *reinterpret_cast<const float4*>(W + row * rowStride + colOff + c4 * 4);
    }
}
__device__ __forceinline__ void commit_w(float* Wst, const float4 pf[8], int tid) {
#pragma unroll
    for (int k = 0; k < 8; k++) {
        int idx4 = tid + k * THREADS;
        *reinterpret_cast<float4*>(Wst + idx4 * 4) = pf[k];
    }
}

// 64x64 = [64x64]@[64x64] GEMM from smem. Thread tile: 4 edges x 8 cols.
// acc returned in registers; optionally gelu+store to Dst.
template <bool DOGELU, bool STORE>
__device__ __forceinline__ void gemm_tile(const float* S, const float* W, float* Dst,
                                          unsigned long long acc[4][4]) {
    const int tid = threadIdx.x;
    const int j0 = (tid & 7) << 3;   // 0..56
    const int e0 = (tid >> 3) << 2;  // 0..60
#pragma unroll
    for (int i = 0; i < 4; i++)
#pragma unroll
        for (int k = 0; k < 4; k++) acc[i][k] = 0ull;

    const float* s = S + e0 * HST;
    const float* wp = W + j0;
#pragma unroll 8
    for (int b = 0; b < 64; b++) {
        float a0 = s[b];
        float a1 = s[HST + b];
        float a2 = s[2 * HST + b];
        float a3 = s[3 * HST + b];
        ulonglong2 w0 = *reinterpret_cast<const ulonglong2*>(wp + (b << 6));
        ulonglong2 w1 = *reinterpret_cast<const ulonglong2*>(wp + (b << 6) + 4);
        unsigned long long aa0 = pack2(a0, a0);
        unsigned long long aa1 = pack2(a1, a1);
        unsigned long long aa2 = pack2(a2, a2);
        unsigned long long aa3 = pack2(a3, a3);
        fma2(acc[0][0], aa0, w0.x); fma2(acc[0][1], aa0, w0.y);
        fma2(acc[0][2], aa0, w1.x); fma2(acc[0][3], aa0, w1.y);
        fma2(acc[1][0], aa1, w0.x); fma2(acc[1][1], aa1, w0.y);
        fma2(acc[1][2], aa1, w1.x); fma2(acc[1][3], aa1, w1.y);
        fma2(acc[2][0], aa2, w0.x); fma2(acc[2][1], aa2, w0.y);
        fma2(acc[2][2], aa2, w1.x); fma2(acc[2][3], aa2, w1.y);
        fma2(acc[3][0], aa3, w0.x); fma2(acc[3][1], aa3, w0.y);
        fma2(acc[3][2], aa3, w1.x); fma2(acc[3][3], aa3, w1.y);
    }
    if (STORE) {
#pragma unroll
        for (int i = 0; i < 4; i++) {
            float* drow = Dst + (e0 + i) * HST + j0;
#pragma unroll
            for (int k = 0; k < 4; k++) {
                float2 v = unpack2(acc[i][k]);
                if (DOGELU) { v.x = gelu_f(v.x); v.y = gelu_f(v.y); }
                drow[2 * k]     = v.x;
                drow[2 * k + 1] = v.y;
            }
        }
    }
}

__global__ __launch_bounds__(THREADS, 3)
void fused_attn_kernel(const float* __restrict__ node_feat,
                       const float* __restrict__ edge_sh,
                       const float* __restrict__ edge_inv,
                       const float* __restrict__ cutoff,
                       const float* __restrict__ Wk1, const float* __restrict__ Wk2,
                       const float* __restrict__ Wk3,
                       const float* __restrict__ Wv1, const float* __restrict__ Wv2,
                       const float* __restrict__ Wv3,
                       const float* __restrict__ W_logit,
                       const float* __restrict__ W_out,
                       const int* __restrict__ edge_src,
                       float* __restrict__ out) {
    extern __shared__ float sm[];
    const int tid = threadIdx.x;
    const int n0 = blockIdx.x * GN;
    const int eg0 = blockIdx.x * EPB;

    float* xs   = sm + OFF_XS;
    float* bufA = sm + OFF_A;
    float* bufB = sm + OFF_B;
    float* Wst  = sm + OFF_W;
    float* qn   = sm + OFF_Q;
    float* shm  = sm + OFF_SH;
    float* WLs  = sm + OFF_WL;
    float* lg   = sm + OFF_LOG;
    float* al   = sm + OFF_AL;
    float* cw   = sm + OFF_CUT;
    int*   srcs = (int*)(sm + OFF_SRC);

    const int j0  = (tid & 7) << 3;
    const int e0t = (tid >> 3) << 2;
    const int nt  = e0t >> 4;          // node index of this thread's edges

    unsigned long long acc[4][4];
    float4 pf[8];

    // ---------- phase 0: loads ----------
    if (tid < EPB) {
        srcs[tid] = edge_src[eg0 + tid];
        cw[tid]   = cutoff[eg0 + tid];
    }
    for (int i = tid; i < GN * 64; i += THREADS) qn[i] = node_feat[n0 * 64 + i];
    for (int i = tid; i < EPB * SDIM; i += THREADS) shm[i] = edge_sh[eg0 * SDIM + i];
    for (int i = tid; i < 512; i += THREADS) WLs[i] = W_logit[i];
    for (int i = tid; i < EPB * 4; i += THREADS) lg[i] = 0.0f;
    for (int i = tid; i < EPB * 64; i += THREADS) {
        int e = i >> 6, c = i & 63;
        bufA[e * HST + c] = edge_inv[eg0 * 64 + i];
    }
    // stage Wk1 directly
    for (int i = tid; i < 1024; i += THREADS) {
        *reinterpret_cast<float4*>(Wst + i * 4) =
            *reinterpret_cast<const float4*>(Wk1 + i * 4);
    }
    __syncthreads();  // srcs ready
    for (int i = tid; i < EPB * 64; i += THREADS) {
        int e = i >> 6, c = i & 63;
        xs[e * HST + c] = node_feat[srcs[e] * 64 + c];
    }
    __syncthreads();

    // ---------- key MLP layers 1,2 ----------
    prefetch_w(pf, Wk2, 64, 0, tid);
    gemm_tile<true, true>(bufA, Wst, bufB, acc);   // h1 = gelu(inv@Wk1)
    __syncthreads();
    commit_w(Wst, pf, tid);
    __syncthreads();

    prefetch_w(pf, Wk3, FDIM, 0, tid);
    gemm_tile<true, true>(bufB, Wst, bufA, acc);   // h2 = gelu(h1@Wk2)
    __syncthreads();
    commit_w(Wst, pf, tid);
    __syncthreads();

    // ---------- key chunks: fold directly into logit partials ----------
    float pl[4][4];
#pragma unroll
    for (int i = 0; i < 4; i++)
#pragma unroll
        for (int h = 0; h < 4; h++) pl[i][h] = 0.f;

    const float* qrow = qn + nt * 64;

    for (int ci = 0; ci < 9; ci++) {
        if (ci < 8) prefetch_w(pf, Wk3, FDIM, (ci + 1) * 64, tid);
        else        prefetch_w(pf, Wv1, 64, 0, tid);
        gemm_tile<false, false>(bufA, Wst, nullptr, acc);
        // fold from registers
        if (ci == 0) {
#pragma unroll
            for (int i = 0; i < 4; i++) {
                int e = e0t + i;
#pragma unroll
                for (int k = 0; k < 4; k++) {
                    float2 v = unpack2(acc[i][k]);
                    int t = j0 + 2 * k;
                    float c0 = qrow[t] * xs[e * HST + t] * v.x;
                    float c1 = qrow[t + 1] * xs[e * HST + t + 1] * v.y;
#pragma unroll
                    for (int h = 0; h < 4; h++)
                        pl[i][h] += c0 * WLs[t * 4 + h] + c1 * WLs[(t + 1) * 4 + h];
                }
            }
        } else {
            int dbase = 8 * (ci - 1);
#pragma unroll
            for (int i = 0; i < 4; i++) {
                int e = e0t + i;
#pragma unroll
                for (int k = 0; k < 4; k++) {
                    float2 v = unpack2(acc[i][k]);
                    int t = j0 + 2 * k;
                    int d0 = dbase + (t >> 3), s0 = t & 7;
                    int d1 = dbase + ((t + 1) >> 3), s1 = (t + 1) & 7;
                    float sv0 = shm[e * SDIM + s0];
                    float sv1 = shm[e * SDIM + s1];
                    float c0 = qrow[d0] * xs[e * HST + d0] * sv0 * sv0 * v.x;
                    float c1 = qrow[d1] * xs[e * HST + d1] * sv1 * sv1 * v.y;
                    int r0 = 64 + d0, r1 = 64 + d1;
#pragma unroll
                    for (int h = 0; h < 4; h++)
                        pl[i][h] += c0 * WLs[r0 * 4 + h] + c1 * WLs[r1 * 4 + h];
                }
            }
        }
        __syncthreads();
        commit_w(Wst, pf, tid);   // stage next chunk / Wv1
        __syncthreads();
    }

    // commit logit partials
#pragma unroll
    for (int i = 0; i < 4; i++)
#pragma unroll
        for (int h = 0; h < 4; h++)
            atomicAdd(&lg[(e0t + i) * 4 + h], pl[i][h]);
    __syncthreads();

    // ---------- softmax per (node, head) + reload edge_inv ----------
    if (tid < GN * HHEAD) {
        int n = tid >> 2, h = tid & 3;
        float mx = -3.0e38f;
        for (int j = 0; j < KEDGE; j++)
            mx = fmaxf(mx, lg[(n * KEDGE + j) * 4 + h]);
        float z = 0.f;
        float ex[KEDGE];
        for (int j = 0; j < KEDGE; j++) {
            int e = n * KEDGE + j;
            ex[j] = cw[e] * expf(lg[e * 4 + h] - mx);
            z += ex[j];
        }
        if (z == 0.f) z = 1.f;
        float inv = 1.f / z;
        for (int j = 0; j < KEDGE; j++)
            al[(n * KEDGE + j) * 4 + h] = sqrtf(ex[j] * inv);
    }
    for (int i = tid; i < EPB * 64; i += THREADS) {
        int e = i >> 6, c = i & 63;
        bufA[e * HST + c] = edge_inv[eg0 * 64 + i];
    }
    __syncthreads();

    // ---------- value MLP layers 1,2 ----------
    prefetch_w(pf, Wv2, 64, 0, tid);
    gemm_tile<true, true>(bufA, Wst, bufB, acc);   // h1v
    __syncthreads();
    commit_w(Wst, pf, tid);
    __syncthreads();

    prefetch_w(pf, Wv3, FDIM, 0, tid);
    gemm_tile<true, true>(bufB, Wst, bufA, acc);   // h2v
    __syncthreads();
    commit_w(Wst, pf, tid);
    // zero node accumulators (bufB region, h1v now dead)
    float* accN = bufB;   // [4][576]
    for (int i = tid; i < GN * FDIM; i += THREADS) accN[i] = 0.f;
    __syncthreads();

    // ---------- value chunks: fold into node acc ----------
    for (int ci = 0; ci < 9; ci++) {
        if (ci < 8) prefetch_w(pf, Wv3, FDIM, (ci + 1) * 64, tid);
        gemm_tile<false, false>(bufA, Wst, nullptr, acc);
#pragma unroll
        for (int k = 0; k < 4; k++) {
            int t = j0 + 2 * k;
            int c0 = ci * 64 + t, c1 = c0 + 1;
            int h0 = c0 / FPH, h1 = c1 / FPH;
            float p0 = 0.f, p1 = 0.f;
            if (ci == 0) {
#pragma unroll
                for (int i = 0; i < 4; i++) {
                    int e = e0t + i;
                    float2 v = unpack2(acc[i][k]);
                    p0 += xs[e * HST + t] * v.x * al[e * 4 + h0];
                    p1 += xs[e * HST + t + 1] * v.y * al[e * 4 + h1];
                }
            } else {
                int dbase = 8 * (ci - 1);
                int d0 = dbase + (t >> 3), s0 = t & 7;
                int d1 = dbase + ((t + 1) >> 3), s1 = (t + 1) & 7;
#pragma unroll
                for (int i = 0; i < 4; i++) {
                    int e = e0t + i;
                    float2 v = unpack2(acc[i][k]);
                    p0 += xs[e * HST + d0] * shm[e * SDIM + s0] * v.x * al[e * 4 + h0];
                    p1 += xs[e * HST + d1] * shm[e * SDIM + s1] * v.y * al[e * 4 + h1];
                }
            }
            atomicAdd(&accN[nt * FDIM + c0], p0);
            atomicAdd(&accN[nt * FDIM + c1], p1);
        }
        __syncthreads();
        if (ci < 8) {
            commit_w(Wst, pf, tid);
            __syncthreads();
        }
    }

    // ---------- epilogue: out[n] = accN[n] @ W_out (576x64) ----------
    {
        int dcol = tid & 63;
        int g = tid >> 6;   // 0 or 1 -> nodes g, g+2
        float s0 = 0.f, s1 = 0.f;
#pragma unroll 8
        for (int c = 0; c < FDIM; c++) {
            float w = W_out[c * 64 + dcol];
            s0 += accN[g * FDIM + c] * w;
            s1 += accN[(g + 2) * FDIM + c] * w;
        }
        out[(n0 + g) * 64 + dcol]     = s0;
        out[(n0 + g + 2) * 64 + dcol] = s1;
    }
}

extern "C" void kernel_launch(void* const* d_in, const int* in_sizes, int n_in,
                              void* d_out, int out_size) {
    const float* node_feat = (const float*)d_in[0];
    const float* edge_sh   = (const float*)d_in[1];
    const float* edge_inv  = (const float*)d_in[2];
    const float* cutoff    = (const float*)d_in[3];
    const float* Wk1       = (const float*)d_in[4];
    const float* Wk2       = (const float*)d_in[5];
    const float* Wk3       = (const float*)d_in[6];
    const float* Wv1       = (const float*)d_in[7];
    const float* Wv2       = (const float*)d_in[8];
    const float* Wv3       = (const float*)d_in[9];
    const float* W_logit   = (const float*)d_in[10];
    const float* W_out     = (const float*)d_in[11];
    const int*   edge_src  = (const int*)d_in[12];
    float* out = (float*)d_out;

    size_t smem = SMEM_FLOATS * sizeof(float);
    cudaFuncSetAttribute(fused_attn_kernel,
                         cudaFuncAttributeMaxDynamicSharedMemorySize, (int)smem);
    fused_attn_kernel<<<NNODES / GN, THREADS, smem>>>(
        node_feat, edge_sh, edge_inv, cutoff,
        Wk1, Wk2, Wk3, Wv1, Wv2, Wv3,
        W_logit, W_out, edge_src, out);
}

// round 3
// speedup vs baseline: 1.4019x; 1.2386x over previous
#include <cuda_runtime.h>
#include <math.h>

// Problem constants
#define NNODES  8192
#define KEDGE   16
#define DDIM    64
#define SDIM    8
#define HHEAD   4
#define FDIM    576
#define FPH     144

// Tiling
#define GN      4
#define EPB     64
#define THREADS 128
#define HST     65      // activation row stride
#define SST     12      // padded sh row stride (float4-aligned, 2-way max)

// smem layout (float offsets)
#define OFF_XS  0                       // [64][65]
#define OFF_A   (OFF_XS + EPB*HST)
#define OFF_B   (OFF_A + EPB*HST)       // later: node acc [4][576]
#define OFF_W   (OFF_B + EPB*HST)
#define OFF_Q   (OFF_W + 64*64)         // [4][64]
#define OFF_SH  (OFF_Q + GN*64)         // [64][12]
#define OFF_WL  (OFF_SH + EPB*SST)      // [128][4]
#define OFF_LOG (OFF_WL + 128*4)        // [64][4]
#define OFF_AL  (OFF_LOG + EPB*4)       // [64][4]
#define OFF_CUT (OFF_AL + EPB*4)        // [64]
#define OFF_SRC (OFF_CUT + EPB)         // [64] ints
#define SMEM_FLOATS (OFF_SRC + EPB)

__device__ __forceinline__ unsigned long long pack2(float x, float y) {
    unsigned long long r;
    asm("mov.b64 %0, {%1, %2};" : "=l"(r) : "f"(x), "f"(y));
    return r;
}
__device__ __forceinline__ void fma2(unsigned long long& d, unsigned long long a, unsigned long long b) {
    asm("fma.rn.f32x2 %0, %1, %2, %0;" : "+l"(d) : "l"(a), "l"(b));
}
__device__ __forceinline__ float2 unpack2(unsigned long long v) {
    float lo, hi;
    asm("mov.b64 {%0, %1}, %2;" : "=f"(lo), "=f"(hi) : "l"(v));
    return make_float2(lo, hi);
}

__device__ __forceinline__ float gelu_f(float x) {
    float u = 0.7978845608028654f * (x + 0.044715f * x * x * x);
    float t;
    asm("tanh.approx.f32 %0, %1;" : "=f"(t) : "f"(u));
    return 0.5f * x * (1.0f + t);
}

__device__ __forceinline__ void prefetch_w(float4 pf[8], const float* __restrict__ W,
                                           int rowStride, int colOff, int tid) {
#pragma unroll
    for (int k = 0; k < 8; k++) {
        int idx4 = tid + k * THREADS;
        int row  = idx4 >> 4;
        int c4   = idx4 & 15;
        pf[k] = *reinterpret_cast<const float4*>(W + row * rowStride + colOff + c4 * 4);
    }
}
__device__ __forceinline__ void commit_w(float* Wst, const float4 pf[8], int tid) {
#pragma unroll
    for (int k = 0; k < 8; k++) {
        int idx4 = tid + k * THREADS;
        *reinterpret_cast<float4*>(Wst + idx4 * 4) = pf[k];
    }
}

// 64x64 GEMM from smem; thread tile 4 edges x 8 cols; acc in registers.
template <bool DOGELU, bool STORE>
__device__ __forceinline__ void gemm_tile(const float* S, const float* W, float* Dst,
                                          unsigned long long acc[4][4]) {
    const int tid = threadIdx.x;
    const int j0 = (tid & 7) << 3;
    const int e0 = (tid >> 3) << 2;
#pragma unroll
    for (int i = 0; i < 4; i++)
#pragma unroll
        for (int k = 0; k < 4; k++) acc[i][k] = 0ull;

    const float* s = S + e0 * HST;
    const float* wp = W + j0;
#pragma unroll 8
    for (int b = 0; b < 64; b++) {
        float a0 = s[b];
        float a1 = s[HST + b];
        float a2 = s[2 * HST + b];
        float a3 = s[3 * HST + b];
        ulonglong2 w0 = *reinterpret_cast<const ulonglong2*>(wp + (b << 6));
        ulonglong2 w1 = *reinterpret_cast<const ulonglong2*>(wp + (b << 6) + 4);
        unsigned long long aa0 = pack2(a0, a0);
        unsigned long long aa1 = pack2(a1, a1);
        unsigned long long aa2 = pack2(a2, a2);
        unsigned long long aa3 = pack2(a3, a3);
        fma2(acc[0][0], aa0, w0.x); fma2(acc[0][1], aa0, w0.y);
        fma2(acc[0][2], aa0, w1.x); fma2(acc[0][3], aa0, w1.y);
        fma2(acc[1][0], aa1, w0.x); fma2(acc[1][1], aa1, w0.y);
        fma2(acc[1][2], aa1, w1.x); fma2(acc[1][3], aa1, w1.y);
        fma2(acc[2][0], aa2, w0.x); fma2(acc[2][1], aa2, w0.y);
        fma2(acc[2][2], aa2, w1.x); fma2(acc[2][3], aa2, w1.y);
        fma2(acc[3][0], aa3, w0.x); fma2(acc[3][1], aa3, w0.y);
        fma2(acc[3][2], aa3, w1.x); fma2(acc[3][3], aa3, w1.y);
    }
    if (STORE) {
#pragma unroll
        for (int i = 0; i < 4; i++) {
            float* drow = Dst + (e0 + i) * HST + j0;
#pragma unroll
            for (int k = 0; k < 4; k++) {
                float2 v = unpack2(acc[i][k]);
                if (DOGELU) { v.x = gelu_f(v.x); v.y = gelu_f(v.y); }
                drow[2 * k]     = v.x;
                drow[2 * k + 1] = v.y;
            }
        }
    }
}

__global__ __launch_bounds__(THREADS, 3)
void fused_attn_kernel(const float* __restrict__ node_feat,
                       const float* __restrict__ edge_sh,
                       const float* __restrict__ edge_inv,
                       const float* __restrict__ cutoff,
                       const float* __restrict__ Wk1, const float* __restrict__ Wk2,
                       const float* __restrict__ Wk3,
                       const float* __restrict__ Wv1, const float* __restrict__ Wv2,
                       const float* __restrict__ Wv3,
                       const float* __restrict__ W_logit,
                       const float* __restrict__ W_out,
                       const int* __restrict__ edge_src,
                       float* __restrict__ out) {
    extern __shared__ float sm[];
    const int tid = threadIdx.x;
    const int n0 = blockIdx.x * GN;
    const int eg0 = blockIdx.x * EPB;

    float* xs   = sm + OFF_XS;
    float* bufA = sm + OFF_A;
    float* bufB = sm + OFF_B;
    float* Wst  = sm + OFF_W;
    float* qn   = sm + OFF_Q;
    float* shm  = sm + OFF_SH;
    float* WLs  = sm + OFF_WL;
    float* lg   = sm + OFF_LOG;
    float* al   = sm + OFF_AL;
    float* cw   = sm + OFF_CUT;
    int*   srcs = (int*)(sm + OFF_SRC);

    const int j0  = (tid & 7) << 3;
    const int e0t = (tid >> 3) << 2;
    const int nt  = e0t >> 4;          // == warp index: warp covers one node

    unsigned long long acc[4][4];
    float4 pf[8];

    // ---------- phase 0: loads ----------
    if (tid < EPB) {
        srcs[tid] = edge_src[eg0 + tid];
        cw[tid]   = cutoff[eg0 + tid];
    }
    for (int i = tid; i < GN * 64; i += THREADS) qn[i] = node_feat[n0 * 64 + i];
    for (int i = tid; i < EPB * SDIM; i += THREADS) {
        int e = i >> 3, s = i & 7;
        shm[e * SST + s] = edge_sh[eg0 * SDIM + i];
    }
    for (int i = tid; i < 512; i += THREADS) WLs[i] = W_logit[i];
    for (int i = tid; i < EPB * 64; i += THREADS) {
        int e = i >> 6, c = i & 63;
        bufA[e * HST + c] = edge_inv[eg0 * 64 + i];
    }
    for (int i = tid; i < 1024; i += THREADS)
        *reinterpret_cast<float4*>(Wst + i * 4) =
            *reinterpret_cast<const float4*>(Wk1 + i * 4);
    __syncthreads();  // srcs ready
    for (int i = tid; i < EPB * 64; i += THREADS) {
        int e = i >> 6, c = i & 63;
        xs[e * HST + c] = node_feat[srcs[e] * 64 + c];
    }
    __syncthreads();

    // ---------- key MLP layers 1,2 ----------
    prefetch_w(pf, Wk2, 64, 0, tid);
    gemm_tile<true, true>(bufA, Wst, bufB, acc);
    __syncthreads();
    commit_w(Wst, pf, tid);
    __syncthreads();

    prefetch_w(pf, Wk3, FDIM, 0, tid);
    gemm_tile<true, true>(bufB, Wst, bufA, acc);
    __syncthreads();
    commit_w(Wst, pf, tid);
    __syncthreads();

    // ---------- key chunks -> logit partials ----------
    float pl[4][4];
#pragma unroll
    for (int i = 0; i < 4; i++)
#pragma unroll
        for (int h = 0; h < 4; h++) pl[i][h] = 0.f;

    const float* qrow = qn + nt * 64;

    for (int ci = 0; ci < 9; ci++) {
        if (ci < 8) prefetch_w(pf, Wk3, FDIM, (ci + 1) * 64, tid);
        else        prefetch_w(pf, Wv1, 64, 0, tid);
        gemm_tile<false, false>(bufA, Wst, nullptr, acc);

        if (ci == 0) {
#pragma unroll
            for (int k = 0; k < 4; k++) {
                int t = j0 + 2 * k;
                float4 wla = *reinterpret_cast<const float4*>(WLs + t * 4);
                float4 wlb = *reinterpret_cast<const float4*>(WLs + t * 4 + 4);
                float qt0 = qrow[t], qt1 = qrow[t + 1];
#pragma unroll
                for (int i = 0; i < 4; i++) {
                    int e = e0t + i;
                    float2 v = unpack2(acc[i][k]);
                    float c0 = qt0 * xs[e * HST + t] * v.x;
                    float c1 = qt1 * xs[e * HST + t + 1] * v.y;
                    pl[i][0] += c0 * wla.x + c1 * wlb.x;
                    pl[i][1] += c0 * wla.y + c1 * wlb.y;
                    pl[i][2] += c0 * wla.z + c1 * wlb.z;
                    pl[i][3] += c0 * wla.w + c1 * wlb.w;
                }
            }
        } else {
            const int d = 8 * (ci - 1) + (tid & 7);   // constant across k
            float4 wl = *reinterpret_cast<const float4*>(WLs + (64 + d) * 4);
            float qd = qrow[d];
#pragma unroll
            for (int i = 0; i < 4; i++) {
                int e = e0t + i;
                float qx = qd * xs[e * HST + d];
                float4 sa = *reinterpret_cast<const float4*>(shm + e * SST);
                float4 sb = *reinterpret_cast<const float4*>(shm + e * SST + 4);
                float s2[8] = {sa.x*sa.x, sa.y*sa.y, sa.z*sa.z, sa.w*sa.w,
                               sb.x*sb.x, sb.y*sb.y, sb.z*sb.z, sb.w*sb.w};
#pragma unroll
                for (int k = 0; k < 4; k++) {
                    float2 v = unpack2(acc[i][k]);
                    float cm = qx * (s2[2*k] * v.x + s2[2*k+1] * v.y);
                    pl[i][0] += cm * wl.x;
                    pl[i][1] += cm * wl.y;
                    pl[i][2] += cm * wl.z;
                    pl[i][3] += cm * wl.w;
                }
            }
        }
        __syncthreads();
        commit_w(Wst, pf, tid);
        __syncthreads();
    }

    // logit reduction over the 8 column-lanes (bits 0-2 of lane id)
#pragma unroll
    for (int m = 1; m < 8; m <<= 1)
#pragma unroll
        for (int i = 0; i < 4; i++)
#pragma unroll
            for (int h = 0; h < 4; h++)
                pl[i][h] += __shfl_xor_sync(0xffffffffu, pl[i][h], m);
    if ((tid & 7) == 0) {
#pragma unroll
        for (int i = 0; i < 4; i++)
            *reinterpret_cast<float4*>(lg + (e0t + i) * 4) =
                make_float4(pl[i][0], pl[i][1], pl[i][2], pl[i][3]);
    }

    // reload edge_inv (bufA's h2k is dead)
    for (int i = tid; i < EPB * 64; i += THREADS) {
        int e = i >> 6, c = i & 63;
        bufA[e * HST + c] = edge_inv[eg0 * 64 + i];
    }
    __syncthreads();

    // ---------- softmax per (node, head) ----------
    if (tid < GN * HHEAD) {
        int n = tid >> 2, h = tid & 3;
        float mx = -3.0e38f;
        for (int j = 0; j < KEDGE; j++)
            mx = fmaxf(mx, lg[(n * KEDGE + j) * 4 + h]);
        float z = 0.f;
        float ex[KEDGE];
        for (int j = 0; j < KEDGE; j++) {
            int e = n * KEDGE + j;
            ex[j] = cw[e] * expf(lg[e * 4 + h] - mx);
            z += ex[j];
        }
        if (z == 0.f) z = 1.f;
        float inv = 1.f / z;
        for (int j = 0; j < KEDGE; j++)
            al[(n * KEDGE + j) * 4 + h] = sqrtf(ex[j] * inv);
    }
    // (al first read after >=2 more barriers)

    // ---------- value MLP layers 1,2 ----------
    prefetch_w(pf, Wv2, 64, 0, tid);
    gemm_tile<true, true>(bufA, Wst, bufB, acc);
    __syncthreads();
    commit_w(Wst, pf, tid);
    __syncthreads();

    prefetch_w(pf, Wv3, FDIM, 0, tid);
    gemm_tile<true, true>(bufB, Wst, bufA, acc);
    __syncthreads();
    commit_w(Wst, pf, tid);
    __syncthreads();

    float* accN = bufB;   // [4][576], fully written by stores below

    // ---------- value chunks -> node accumulators ----------
    for (int ci = 0; ci < 9; ci++) {
        if (ci < 8) prefetch_w(pf, Wv3, FDIM, (ci + 1) * 64, tid);
        gemm_tile<false, false>(bufA, Wst, nullptr, acc);

        float pk0[4] = {0.f, 0.f, 0.f, 0.f};
        float pk1[4] = {0.f, 0.f, 0.f, 0.f};
        const int clo = ci * 64 + j0;

        if (ci == 0) {
            // head 0 for all cols < 64
#pragma unroll
            for (int i = 0; i < 4; i++) {
                int e = e0t + i;
                float av = al[e * 4 + 0];
#pragma unroll
                for (int k = 0; k < 4; k++) {
                    int t = j0 + 2 * k;
                    float2 v = unpack2(acc[i][k]);
                    pk0[k] += xs[e * HST + t] * v.x * av;
                    pk1[k] += xs[e * HST + t + 1] * v.y * av;
                }
            }
        } else {
            const int d = 8 * (ci - 1) + (tid & 7);
            const int ha = clo / FPH;
            const int hb = (clo + 7) / FPH;
            const int thr = (ha + 1) * FPH;
#pragma unroll
            for (int i = 0; i < 4; i++) {
                int e = e0t + i;
                float xa = xs[e * HST + d];
                float4 sa = *reinterpret_cast<const float4*>(shm + e * SST);
                float4 sb = *reinterpret_cast<const float4*>(shm + e * SST + 4);
                float s8[8] = {sa.x, sa.y, sa.z, sa.w, sb.x, sb.y, sb.z, sb.w};
                float aA = al[e * 4 + ha];
                float aB = al[e * 4 + hb];
#pragma unroll
                for (int k = 0; k < 4; k++) {
                    float2 v = unpack2(acc[i][k]);
                    float a0 = (clo + 2 * k     >= thr) ? aB : aA;
                    float a1 = (clo + 2 * k + 1 >= thr) ? aB : aA;
                    pk0[k] += xa * s8[2*k]   * v.x * a0;
                    pk1[k] += xa * s8[2*k+1] * v.y * a1;
                }
            }
        }
        // reduce over the 4 edge-groups (lane bits 3,4) -> 16-edge node sum
#pragma unroll
        for (int k = 0; k < 4; k++) {
            pk0[k] += __shfl_xor_sync(0xffffffffu, pk0[k], 8);
            pk0[k] += __shfl_xor_sync(0xffffffffu, pk0[k], 16);
            pk1[k] += __shfl_xor_sync(0xffffffffu, pk1[k], 8);
            pk1[k] += __shfl_xor_sync(0xffffffffu, pk1[k], 16);
        }
        if ((tid & 31) < 8) {
#pragma unroll
            for (int k = 0; k < 4; k++)
                *reinterpret_cast<float2*>(accN + nt * FDIM + clo + 2 * k) =
                    make_float2(pk0[k], pk1[k]);
        }
        __syncthreads();
        if (ci < 8) {
            commit_w(Wst, pf, tid);
            __syncthreads();
        }
    }

    // ---------- epilogue: out[n] = accN[n] @ W_out ----------
    {
        int dcol = tid & 63;
        int g = tid >> 6;   // 0 or 1 -> nodes g, g+2
        float s0 = 0.f, s1 = 0.f;
#pragma unroll 8
        for (int c = 0; c < FDIM; c++) {
            float w = W_out[c * 64 + dcol];
            s0 += accN[g * FDIM + c] * w;
            s1 += accN[(g + 2) * FDIM + c] * w;
        }
        out[(n0 + g) * 64 + dcol]     = s0;
        out[(n0 + g + 2) * 64 + dcol] = s1;
    }
}

extern "C" void kernel_launch(void* const* d_in, const int* in_sizes, int n_in,
                              void* d_out, int out_size) {
    const float* node_feat = (const float*)d_in[0];
    const float* edge_sh   = (const float*)d_in[1];
    const float* edge_inv  = (const float*)d_in[2];
    const float* cutoff    = (const float*)d_in[3];
    const float* Wk1       = (const float*)d_in[4];
    const float* Wk2       = (const float*)d_in[5];
    const float* Wk3       = (const float*)d_in[6];
    const float* Wv1       = (const float*)d_in[7];
    const float* Wv2       = (const float*)d_in[8];
    const float* Wv3       = (const float*)d_in[9];
    const float* W_logit   = (const float*)d_in[10];
    const float* W_out     = (const float*)d_in[11];
    const int*   edge_src  = (const int*)d_in[12];
    float* out = (float*)d_out;

    size_t smem = SMEM_FLOATS * sizeof(float);
    cudaFuncSetAttribute(fused_attn_kernel,
                         cudaFuncAttributeMaxDynamicSharedMemorySize, (int)smem);
    fused_attn_kernel<<<NNODES / GN, THREADS, smem>>>(
        node_feat, edge_sh, edge_inv, cutoff,
        Wk1, Wk2, Wk3, Wv1, Wv2, Wv3,
        W_logit, W_out, edge_src, out);
}

// round 4
// speedup vs baseline: 1.4034x; 1.0010x over previous
#include <cuda_runtime.h>
#include <math.h>

// Problem constants
#define NNODES  8192
#define KEDGE   16
#define DDIM    64
#define SDIM    8
#define HHEAD   4
#define FDIM    576
#define FPH     144

// Tiling
#define GN      4
#define EPB     64
#define THREADS 128
#define HST     65      // activation row stride
#define SST     12      // padded sh row stride (float4-aligned, 2-way max)

// smem layout (float offsets)
#define OFF_XS  0                       // [64][65]
#define OFF_A   (OFF_XS + EPB*HST)
#define OFF_B   (OFF_A + EPB*HST)       // later: node acc [4][576]
#define OFF_W   (OFF_B + EPB*HST)
#define OFF_Q   (OFF_W + 64*64)         // [4][64]
#define OFF_SH  (OFF_Q + GN*64)         // [64][12]
#define OFF_WL  (OFF_SH + EPB*SST)      // [128][4]
#define OFF_LOG (OFF_WL + 128*4)        // [64][4]
#define OFF_AL  (OFF_LOG + EPB*4)       // [64][4]
#define OFF_CUT (OFF_AL + EPB*4)        // [64]
#define OFF_SRC (OFF_CUT + EPB)         // [64] ints
#define SMEM_FLOATS (OFF_SRC + EPB)

__device__ __forceinline__ unsigned long long pack2(float x, float y) {
    unsigned long long r;
    asm("mov.b64 %0, {%1, %2};" : "=l"(r) : "f"(x), "f"(y));
    return r;
}
__device__ __forceinline__ void fma2(unsigned long long& d, unsigned long long a, unsigned long long b) {
    asm("fma.rn.f32x2 %0, %1, %2, %0;" : "+l"(d) : "l"(a), "l"(b));
}
__device__ __forceinline__ float2 unpack2(unsigned long long v) {
    float lo, hi;
    asm("mov.b64 {%0, %1}, %2;" : "=f"(lo), "=f"(hi) : "l"(v));
    return make_float2(lo, hi);
}

__device__ __forceinline__ float gelu_f(float x) {
    float u = 0.7978845608028654f * (x + 0.044715f * x * x * x);
    float t;
    asm("tanh.approx.f32 %0, %1;" : "=f"(t) : "f"(u));
    return 0.5f * x * (1.0f + t);
}

__device__ __forceinline__ void prefetch_w(float4 pf[8], const float* __restrict__ W,
                                           int rowStride, int colOff, int tid) {
#pragma unroll
    for (int k = 0; k < 8; k++) {
        int idx4 = tid + k * THREADS;
        int row  = idx4 >> 4;
        int c4   = idx4 & 15;
        pf[k] = *reinterpret_cast<const float4*>(W + row * rowStride + colOff + c4 * 4);
    }
}
__device__ __forceinline__ void commit_w(float* Wst, const float4 pf[8], int tid) {
#pragma unroll
    for (int k = 0; k < 8; k++) {
        int idx4 = tid + k * THREADS;
        *reinterpret_cast<float4*>(Wst + idx4 * 4) = pf[k];
    }
}

// 64x64 GEMM from smem; thread tile 4 edges x 8 cols; acc in registers.
template <bool DOGELU, bool STORE>
__device__ __forceinline__ void gemm_tile(const float* S, const float* W, float* Dst,
                                          unsigned long long acc[4][4]) {
    const int tid = threadIdx.x;
    const int j0 = (tid & 7) << 3;
    const int e0 = (tid >> 3) << 2;
#pragma unroll
    for (int i = 0; i < 4; i++)
#pragma unroll
        for (int k = 0; k < 4; k++) acc[i][k] = 0ull;

    const float* s = S + e0 * HST;
    const float* wp = W + j0;
#pragma unroll 8
    for (int b = 0; b < 64; b++) {
        float a0 = s[b];
        float a1 = s[HST + b];
        float a2 = s[2 * HST + b];
        float a3 = s[3 * HST + b];
        ulonglong2 w0 = *reinterpret_cast<const ulonglong2*>(wp + (b << 6));
        ulonglong2 w1 = *reinterpret_cast<const ulonglong2*>(wp + (b << 6) + 4);
        unsigned long long aa0 = pack2(a0, a0);
        unsigned long long aa1 = pack2(a1, a1);
        unsigned long long aa2 = pack2(a2, a2);
        unsigned long long aa3 = pack2(a3, a3);
        fma2(acc[0][0], aa0, w0.x); fma2(acc[0][1], aa0, w0.y);
        fma2(acc[0][2], aa0, w1.x); fma2(acc[0][3], aa0, w1.y);
        fma2(acc[1][0], aa1, w0.x); fma2(acc[1][1], aa1, w0.y);
        fma2(acc[1][2], aa1, w1.x); fma2(acc[1][3], aa1, w1.y);
        fma2(acc[2][0], aa2, w0.x); fma2(acc[2][1], aa2, w0.y);
        fma2(acc[2][2], aa2, w1.x); fma2(acc[2][3], aa2, w1.y);
        fma2(acc[3][0], aa3, w0.x); fma2(acc[3][1], aa3, w0.y);
        fma2(acc[3][2], aa3, w1.x); fma2(acc[3][3], aa3, w1.y);
    }
    if (STORE) {
#pragma unroll
        for (int i = 0; i < 4; i++) {
            float* drow = Dst + (e0 + i) * HST + j0;
#pragma unroll
            for (int k = 0; k < 4; k++) {
                float2 v = unpack2(acc[i][k]);
                if (DOGELU) { v.x = gelu_f(v.x); v.y = gelu_f(v.y); }
                drow[2 * k]     = v.x;
                drow[2 * k + 1] = v.y;
            }
        }
    }
}

__global__ __launch_bounds__(THREADS, 3)
void fused_attn_kernel(const float* __restrict__ node_feat,
                       const float* __restrict__ edge_sh,
                       const float* __restrict__ edge_inv,
                       const float* __restrict__ cutoff,
                       const float* __restrict__ Wk1, const float* __restrict__ Wk2,
                       const float* __restrict__ Wk3,
                       const float* __restrict__ Wv1, const float* __restrict__ Wv2,
                       const float* __restrict__ Wv3,
                       const float* __restrict__ W_logit,
                       const float* __restrict__ W_out,
                       const int* __restrict__ edge_src,
                       float* __restrict__ out) {
    extern __shared__ float sm[];
    const int tid = threadIdx.x;
    const int n0 = blockIdx.x * GN;
    const int eg0 = blockIdx.x * EPB;

    float* xs   = sm + OFF_XS;
    float* bufA = sm + OFF_A;
    float* bufB = sm + OFF_B;
    float* Wst  = sm + OFF_W;
    float* qn   = sm + OFF_Q;
    float* shm  = sm + OFF_SH;
    float* WLs  = sm + OFF_WL;
    float* lg   = sm + OFF_LOG;
    float* al   = sm + OFF_AL;
    float* cw   = sm + OFF_CUT;
    int*   srcs = (int*)(sm + OFF_SRC);

    const int j0  = (tid & 7) << 3;
    const int e0t = (tid >> 3) << 2;
    const int nt  = e0t >> 4;          // == warp index: warp covers one node

    unsigned long long acc[4][4];
    float4 pf[8];

    // ---------- phase 0: loads ----------
    if (tid < EPB) {
        srcs[tid] = edge_src[eg0 + tid];
        cw[tid]   = cutoff[eg0 + tid];
    }
    for (int i = tid; i < GN * 64; i += THREADS) qn[i] = node_feat[n0 * 64 + i];
    for (int i = tid; i < EPB * SDIM; i += THREADS) {
        int e = i >> 3, s = i & 7;
        shm[e * SST + s] = edge_sh[eg0 * SDIM + i];
    }
    for (int i = tid; i < 512; i += THREADS) WLs[i] = W_logit[i];
    for (int i = tid; i < EPB * 64; i += THREADS) {
        int e = i >> 6, c = i & 63;
        bufA[e * HST + c] = edge_inv[eg0 * 64 + i];
    }
    for (int i = tid; i < 1024; i += THREADS)
        *reinterpret_cast<float4*>(Wst + i * 4) =
            *reinterpret_cast<const float4*>(Wk1 + i * 4);
    __syncthreads();  // srcs ready
    for (int i = tid; i < EPB * 64; i += THREADS) {
        int e = i >> 6, c = i & 63;
        xs[e * HST + c] = node_feat[srcs[e] * 64 + c];
    }
    __syncthreads();

    // ---------- key MLP layers 1,2 ----------
    prefetch_w(pf, Wk2, 64, 0, tid);
    gemm_tile<true, true>(bufA, Wst, bufB, acc);
    __syncthreads();
    commit_w(Wst, pf, tid);
    __syncthreads();

    prefetch_w(pf, Wk3, FDIM, 0, tid);
    gemm_tile<true, true>(bufB, Wst, bufA, acc);
    __syncthreads();
    commit_w(Wst, pf, tid);
    __syncthreads();

    // ---------- key chunks -> logit partials ----------
    float pl[4][4];
#pragma unroll
    for (int i = 0; i < 4; i++)
#pragma unroll
        for (int h = 0; h < 4; h++) pl[i][h] = 0.f;

    const float* qrow = qn + nt * 64;

    for (int ci = 0; ci < 9; ci++) {
        if (ci < 8) prefetch_w(pf, Wk3, FDIM, (ci + 1) * 64, tid);
        else        prefetch_w(pf, Wv1, 64, 0, tid);
        gemm_tile<false, false>(bufA, Wst, nullptr, acc);

        if (ci == 0) {
#pragma unroll
            for (int k = 0; k < 4; k++) {
                int t = j0 + 2 * k;
                float4 wla = *reinterpret_cast<const float4*>(WLs + t * 4);
                float4 wlb = *reinterpret_cast<const float4*>(WLs + t * 4 + 4);
                float qt0 = qrow[t], qt1 = qrow[t + 1];
#pragma unroll
                for (int i = 0; i < 4; i++) {
                    int e = e0t + i;
                    float2 v = unpack2(acc[i][k]);
                    float c0 = qt0 * xs[e * HST + t] * v.x;
                    float c1 = qt1 * xs[e * HST + t + 1] * v.y;
                    pl[i][0] += c0 * wla.x + c1 * wlb.x;
                    pl[i][1] += c0 * wla.y + c1 * wlb.y;
                    pl[i][2] += c0 * wla.z + c1 * wlb.z;
                    pl[i][3] += c0 * wla.w + c1 * wlb.w;
                }
            }
        } else {
            const int d = 8 * (ci - 1) + (tid & 7);   // constant across k
            float4 wl = *reinterpret_cast<const float4*>(WLs + (64 + d) * 4);
            float qd = qrow[d];
#pragma unroll
            for (int i = 0; i < 4; i++) {
                int e = e0t + i;
                float qx = qd * xs[e * HST + d];
                float4 sa = *reinterpret_cast<const float4*>(shm + e * SST);
                float4 sb = *reinterpret_cast<const float4*>(shm + e * SST + 4);
                float s2[8] = {sa.x*sa.x, sa.y*sa.y, sa.z*sa.z, sa.w*sa.w,
                               sb.x*sb.x, sb.y*sb.y, sb.z*sb.z, sb.w*sb.w};
#pragma unroll
                for (int k = 0; k < 4; k++) {
                    float2 v = unpack2(acc[i][k]);
                    float cm = qx * (s2[2*k] * v.x + s2[2*k+1] * v.y);
                    pl[i][0] += cm * wl.x;
                    pl[i][1] += cm * wl.y;
                    pl[i][2] += cm * wl.z;
                    pl[i][3] += cm * wl.w;
                }
            }
        }
        __syncthreads();
        commit_w(Wst, pf, tid);
        __syncthreads();
    }

    // logit reduction over the 8 column-lanes (bits 0-2 of lane id)
#pragma unroll
    for (int m = 1; m < 8; m <<= 1)
#pragma unroll
        for (int i = 0; i < 4; i++)
#pragma unroll
            for (int h = 0; h < 4; h++)
                pl[i][h] += __shfl_xor_sync(0xffffffffu, pl[i][h], m);
    if ((tid & 7) == 0) {
#pragma unroll
        for (int i = 0; i < 4; i++)
            *reinterpret_cast<float4*>(lg + (e0t + i) * 4) =
                make_float4(pl[i][0], pl[i][1], pl[i][2], pl[i][3]);
    }

    // reload edge_inv (bufA's h2k is dead)
    for (int i = tid; i < EPB * 64; i += THREADS) {
        int e = i >> 6, c = i & 63;
        bufA[e * HST + c] = edge_inv[eg0 * 64 + i];
    }
    __syncthreads();

    // ---------- softmax per (node, head) ----------
    if (tid < GN * HHEAD) {
        int n = tid >> 2, h = tid & 3;
        float mx = -3.0e38f;
        for (int j = 0; j < KEDGE; j++)
            mx = fmaxf(mx, lg[(n * KEDGE + j) * 4 + h]);
        float z = 0.f;
        float ex[KEDGE];
        for (int j = 0; j < KEDGE; j++) {
            int e = n * KEDGE + j;
            ex[j] = cw[e] * expf(lg[e * 4 + h] - mx);
            z += ex[j];
        }
        if (z == 0.f) z = 1.f;
        float inv = 1.f / z;
        for (int j = 0; j < KEDGE; j++)
            al[(n * KEDGE + j) * 4 + h] = sqrtf(ex[j] * inv);
    }
    // (al first read after >=2 more barriers)

    // ---------- value MLP layers 1,2 ----------
    prefetch_w(pf, Wv2, 64, 0, tid);
    gemm_tile<true, true>(bufA, Wst, bufB, acc);
    __syncthreads();
    commit_w(Wst, pf, tid);
    __syncthreads();

    prefetch_w(pf, Wv3, FDIM, 0, tid);
    gemm_tile<true, true>(bufB, Wst, bufA, acc);
    __syncthreads();
    commit_w(Wst, pf, tid);
    __syncthreads();

    float* accN = bufB;   // [4][576], fully written by stores below

    // ---------- value chunks -> node accumulators ----------
    for (int ci = 0; ci < 9; ci++) {
        if (ci < 8) prefetch_w(pf, Wv3, FDIM, (ci + 1) * 64, tid);
        gemm_tile<false, false>(bufA, Wst, nullptr, acc);

        float pk0[4] = {0.f, 0.f, 0.f, 0.f};
        float pk1[4] = {0.f, 0.f, 0.f, 0.f};
        const int clo = ci * 64 + j0;

        if (ci == 0) {
            // head 0 for all cols < 64
#pragma unroll
            for (int i = 0; i < 4; i++) {
                int e = e0t + i;
                float av = al[e * 4 + 0];
#pragma unroll
                for (int k = 0; k < 4; k++) {
                    int t = j0 + 2 * k;
                    float2 v = unpack2(acc[i][k]);
                    pk0[k] += xs[e * HST + t] * v.x * av;
                    pk1[k] += xs[e * HST + t + 1] * v.y * av;
                }
            }
        } else {
            const int d = 8 * (ci - 1) + (tid & 7);
            const int ha = clo / FPH;
            const int hb = (clo + 7) / FPH;
            const int thr = (ha + 1) * FPH;
#pragma unroll
            for (int i = 0; i < 4; i++) {
                int e = e0t + i;
                float xa = xs[e * HST + d];
                float4 sa = *reinterpret_cast<const float4*>(shm + e * SST);
                float4 sb = *reinterpret_cast<const float4*>(shm + e * SST + 4);
                float s8[8] = {sa.x, sa.y, sa.z, sa.w, sb.x, sb.y, sb.z, sb.w};
                float aA = al[e * 4 + ha];
                float aB = al[e * 4 + hb];
#pragma unroll
                for (int k = 0; k < 4; k++) {
                    float2 v = unpack2(acc[i][k]);
                    float a0 = (clo + 2 * k     >= thr) ? aB : aA;
                    float a1 = (clo + 2 * k + 1 >= thr) ? aB : aA;
                    pk0[k] += xa * s8[2*k]   * v.x * a0;
                    pk1[k] += xa * s8[2*k+1] * v.y * a1;
                }
            }
        }
        // reduce over the 4 edge-groups (lane bits 3,4) -> 16-edge node sum
#pragma unroll
        for (int k = 0; k < 4; k++) {
            pk0[k] += __shfl_xor_sync(0xffffffffu, pk0[k], 8);
            pk0[k] += __shfl_xor_sync(0xffffffffu, pk0[k], 16);
            pk1[k] += __shfl_xor_sync(0xffffffffu, pk1[k], 8);
            pk1[k] += __shfl_xor_sync(0xffffffffu, pk1[k], 16);
        }
        if ((tid & 31) < 8) {
#pragma unroll
            for (int k = 0; k < 4; k++)
                *reinterpret_cast<float2*>(accN + nt * FDIM + clo + 2 * k) =
                    make_float2(pk0[k], pk1[k]);
        }
        __syncthreads();
        if (ci < 8) {
            commit_w(Wst, pf, tid);
            __syncthreads();
        }
    }

    // ---------- epilogue: out[n] = accN[n] @ W_out ----------
    {
        int dcol = tid & 63;
        int g = tid >> 6;   // 0 or 1 -> nodes g, g+2
        float s0 = 0.f, s1 = 0.f;
#pragma unroll 8
        for (int c = 0; c < FDIM; c++) {
            float w = W_out[c * 64 + dcol];
            s0 += accN[g * FDIM + c] * w;
            s1 += accN[(g + 2) * FDIM + c] * w;
        }
        out[(n0 + g) * 64 + dcol]     = s0;
        out[(n0 + g + 2) * 64 + dcol] = s1;
    }
}

extern "C" void kernel_launch(void* const* d_in, const int* in_sizes, int n_in,
                              void* d_out, int out_size) {
    const float* node_feat = (const float*)d_in[0];
    const float* edge_sh   = (const float*)d_in[1];
    const float* edge_inv  = (const float*)d_in[2];
    const float* cutoff    = (const float*)d_in[3];
    const float* Wk1       = (const float*)d_in[4];
    const float* Wk2       = (const float*)d_in[5];
    const float* Wk3       = (const float*)d_in[6];
    const float* Wv1       = (const float*)d_in[7];
    const float* Wv2       = (const float*)d_in[8];
    const float* Wv3       = (const float*)d_in[9];
    const float* W_logit   = (const float*)d_in[10];
    const float* W_out     = (const float*)d_in[11];
    const int*   edge_src  = (const int*)d_in[12];
    float* out = (float*)d_out;

    size_t smem = SMEM_FLOATS * sizeof(float);
    cudaFuncSetAttribute(fused_attn_kernel,
                         cudaFuncAttributeMaxDynamicSharedMemorySize, (int)smem);
    fused_attn_kernel<<<NNODES / GN, THREADS, smem>>>(
        node_feat, edge_sh, edge_inv, cutoff,
        Wk1, Wk2, Wk3, Wv1, Wv2, Wv3,
        W_logit, W_out, edge_src, out);
}

// round 5
// speedup vs baseline: 1.4461x; 1.0305x over previous
#include <cuda_runtime.h>
#include <math.h>

// Problem constants
#define NNODES  8192
#define KEDGE   16
#define DDIM    64
#define SDIM    8
#define HHEAD   4
#define FDIM    576
#define FPH     144

// Tiling
#define GN      4
#define EPB     64
#define THREADS 128

// Transposed activation tiles: T[c][e], 64x64, XOR swizzle on edge quads.
// e_phys = e ^ (((c>>3)&7)<<2)

// smem layout (float offsets)
#define OFF_XS  0                       // [64c][64e] transposed
#define OFF_A   (OFF_XS + 4096)
#define OFF_B   (OFF_A + 4096)          // later: node acc [4][576]
#define OFF_W   (OFF_B + 4096)          // [64][64] weight stage
#define OFF_Q   (OFF_W + 4096)          // [4][64]
#define OFF_SH  (OFF_Q + 256)           // [8s][64e] transposed
#define OFF_WL  (OFF_SH + 512)          // [128][4]
#define OFF_LOG (OFF_WL + 512)          // [64][4]
#define OFF_AL  (OFF_LOG + 256)         // [4h][64e] transposed
#define OFF_CUT (OFF_AL + 256)          // [64]
#define OFF_SRC (OFF_CUT + 64)          // [64] ints
#define SMEM_FLOATS (OFF_SRC + 64)      // 18304 floats = 73216 B

__device__ __forceinline__ unsigned long long pack2(float x, float y) {
    unsigned long long r;
    asm("mov.b64 %0, {%1, %2};" : "=l"(r) : "f"(x), "f"(y));
    return r;
}
__device__ __forceinline__ void fma2(unsigned long long& d, unsigned long long a, unsigned long long b) {
    asm("fma.rn.f32x2 %0, %1, %2, %0;" : "+l"(d) : "l"(a), "l"(b));
}
__device__ __forceinline__ float2 unpack2(unsigned long long v) {
    float lo, hi;
    asm("mov.b64 {%0, %1}, %2;" : "=f"(lo), "=f"(hi) : "l"(v));
    return make_float2(lo, hi);
}

__device__ __forceinline__ float gelu_f(float x) {
    float u = 0.7978845608028654f * (x + 0.044715f * x * x * x);
    float t;
    asm("tanh.approx.f32 %0, %1;" : "=f"(t) : "f"(u));
    return 0.5f * x * (1.0f + t);
}

__device__ __forceinline__ void prefetch_w(float4 pf[8], const float* __restrict__ W,
                                           int rowStride, int colOff, int tid) {
#pragma unroll
    for (int k = 0; k < 8; k++) {
        int idx4 = tid + k * THREADS;
        int row  = idx4 >> 4;
        int c4   = idx4 & 15;
        pf[k] = *reinterpret_cast<const float4*>(W + row * rowStride + colOff + c4 * 4);
    }
}
__device__ __forceinline__ void commit_w(float* Wst, const float4 pf[8], int tid) {
#pragma unroll
    for (int k = 0; k < 8; k++) {
        int idx4 = tid + k * THREADS;
        *reinterpret_cast<float4*>(Wst + idx4 * 4) = pf[k];
    }
}

// 64x64 GEMM, A transposed [c][e] (swizzled), W [b][64].
// Thread tile 4 edges x 8 cols; acc in registers; optional transposed store.
template <bool DOGELU, bool STORE>
__device__ __forceinline__ void gemm_tile_t(const float* A, const float* W, float* Dst,
                                            unsigned long long acc[4][4]) {
    const int tid = threadIdx.x;
    const int j0 = (tid & 7) << 3;
    const int e0 = (tid >> 3) << 2;
#pragma unroll
    for (int i = 0; i < 4; i++)
#pragma unroll
        for (int k = 0; k < 4; k++) acc[i][k] = 0ull;

    const float* wp = W + j0;
#pragma unroll
    for (int bb = 0; bb < 8; bb++) {
        const float* ap = A + bb * 512 + (e0 ^ (bb << 2));
#pragma unroll
        for (int b2 = 0; b2 < 8; b2++) {
            const int b = bb * 8 + b2;
            float4 av = *reinterpret_cast<const float4*>(ap + b2 * 64);
            ulonglong2 w0 = *reinterpret_cast<const ulonglong2*>(wp + (b << 6));
            ulonglong2 w1 = *reinterpret_cast<const ulonglong2*>(wp + (b << 6) + 4);
            unsigned long long aa0 = pack2(av.x, av.x);
            unsigned long long aa1 = pack2(av.y, av.y);
            unsigned long long aa2 = pack2(av.z, av.z);
            unsigned long long aa3 = pack2(av.w, av.w);
            fma2(acc[0][0], aa0, w0.x); fma2(acc[0][1], aa0, w0.y);
            fma2(acc[0][2], aa0, w1.x); fma2(acc[0][3], aa0, w1.y);
            fma2(acc[1][0], aa1, w0.x); fma2(acc[1][1], aa1, w0.y);
            fma2(acc[1][2], aa1, w1.x); fma2(acc[1][3], aa1, w1.y);
            fma2(acc[2][0], aa2, w0.x); fma2(acc[2][1], aa2, w0.y);
            fma2(acc[2][2], aa2, w1.x); fma2(acc[2][3], aa2, w1.y);
            fma2(acc[3][0], aa3, w0.x); fma2(acc[3][1], aa3, w0.y);
            fma2(acc[3][2], aa3, w1.x); fma2(acc[3][3], aa3, w1.y);
        }
    }
    if (STORE) {
        const int exs = e0 ^ ((tid & 7) << 2);   // swz(c) for c in [j0, j0+8)
#pragma unroll
        for (int k = 0; k < 4; k++) {
            float2 u0 = unpack2(acc[0][k]);
            float2 u1 = unpack2(acc[1][k]);
            float2 u2 = unpack2(acc[2][k]);
            float2 u3 = unpack2(acc[3][k]);
            if (DOGELU) {
                u0.x = gelu_f(u0.x); u0.y = gelu_f(u0.y);
                u1.x = gelu_f(u1.x); u1.y = gelu_f(u1.y);
                u2.x = gelu_f(u2.x); u2.y = gelu_f(u2.y);
                u3.x = gelu_f(u3.x); u3.y = gelu_f(u3.y);
            }
            const int c0 = j0 + 2 * k;
            *reinterpret_cast<float4*>(Dst + c0 * 64 + exs) =
                make_float4(u0.x, u1.x, u2.x, u3.x);
            *reinterpret_cast<float4*>(Dst + (c0 + 1) * 64 + exs) =
                make_float4(u0.y, u1.y, u2.y, u3.y);
        }
    }
}

__global__ __launch_bounds__(THREADS, 3)
void fused_attn_kernel(const float* __restrict__ node_feat,
                       const float* __restrict__ edge_sh,
                       const float* __restrict__ edge_inv,
                       const float* __restrict__ cutoff,
                       const float* __restrict__ Wk1, const float* __restrict__ Wk2,
                       const float* __restrict__ Wk3,
                       const float* __restrict__ Wv1, const float* __restrict__ Wv2,
                       const float* __restrict__ Wv3,
                       const float* __restrict__ W_logit,
                       const float* __restrict__ W_out,
                       const int* __restrict__ edge_src,
                       float* __restrict__ out) {
    extern __shared__ float sm[];
    const int tid = threadIdx.x;
    const int n0 = blockIdx.x * GN;
    const int eg0 = blockIdx.x * EPB;

    float* xs   = sm + OFF_XS;   // transposed [c][e]
    float* bufA = sm + OFF_A;
    float* bufB = sm + OFF_B;
    float* Wst  = sm + OFF_W;
    float* qn   = sm + OFF_Q;
    float* shm  = sm + OFF_SH;   // transposed [s][e]
    float* WLs  = sm + OFF_WL;
    float* lg   = sm + OFF_LOG;
    float* al   = sm + OFF_AL;   // transposed [h][e]
    float* cw   = sm + OFF_CUT;
    int*   srcs = (int*)(sm + OFF_SRC);

    const int j0  = (tid & 7) << 3;
    const int e0t = (tid >> 3) << 2;
    const int nt  = e0t >> 4;           // warp id == node index
    const int exs = e0t ^ ((tid & 7) << 2);   // swizzled edge base for cols [j0,j0+8)

    unsigned long long acc[4][4];
    float4 pf[8];

    // ---------- phase 0: loads ----------
    if (tid < EPB) {
        srcs[tid] = edge_src[eg0 + tid];
        cw[tid]   = cutoff[eg0 + tid];
    }
    for (int i = tid; i < GN * 64; i += THREADS) qn[i] = node_feat[n0 * 64 + i];
    for (int i = tid; i < EPB * SDIM; i += THREADS) {
        int e = i >> 3, s = i & 7;
        shm[s * 64 + e] = edge_sh[eg0 * SDIM + i];
    }
    for (int i = tid; i < 512; i += THREADS) WLs[i] = W_logit[i];
    // edge_inv -> bufA transposed+swizzled
    for (int idx = tid; idx < 1024; idx += THREADS) {
        int e  = idx & 63;
        int c4 = (idx >> 6) << 2;
        float4 v = *reinterpret_cast<const float4*>(edge_inv + (eg0 + e) * 64 + c4);
        int ep = e ^ (((c4 >> 3) & 7) << 2);
        bufA[(c4 + 0) * 64 + ep] = v.x;
        bufA[(c4 + 1) * 64 + ep] = v.y;
        bufA[(c4 + 2) * 64 + ep] = v.z;
        bufA[(c4 + 3) * 64 + ep] = v.w;
    }
    for (int i = tid; i < 1024; i += THREADS)
        *reinterpret_cast<float4*>(Wst + i * 4) =
            *reinterpret_cast<const float4*>(Wk1 + i * 4);
    __syncthreads();  // srcs ready
    // x_src -> xs transposed+swizzled
    for (int idx = tid; idx < 1024; idx += THREADS) {
        int e  = idx & 63;
        int c4 = (idx >> 6) << 2;
        float4 v = *reinterpret_cast<const float4*>(node_feat + srcs[e] * 64 + c4);
        int ep = e ^ (((c4 >> 3) & 7) << 2);
        xs[(c4 + 0) * 64 + ep] = v.x;
        xs[(c4 + 1) * 64 + ep] = v.y;
        xs[(c4 + 2) * 64 + ep] = v.z;
        xs[(c4 + 3) * 64 + ep] = v.w;
    }
    __syncthreads();

    // ---------- key MLP layers 1,2 ----------
    prefetch_w(pf, Wk2, 64, 0, tid);
    gemm_tile_t<true, true>(bufA, Wst, bufB, acc);
    __syncthreads();
    commit_w(Wst, pf, tid);
    __syncthreads();

    prefetch_w(pf, Wk3, FDIM, 0, tid);
    gemm_tile_t<true, true>(bufB, Wst, bufA, acc);
    __syncthreads();
    commit_w(Wst, pf, tid);
    __syncthreads();

    // ---------- key chunks -> logit partials ----------
    float pl[4][4];
#pragma unroll
    for (int i = 0; i < 4; i++)
#pragma unroll
        for (int h = 0; h < 4; h++) pl[i][h] = 0.f;

    const float* qrow = qn + nt * 64;

    for (int ci = 0; ci < 9; ci++) {
        if (ci < 8) prefetch_w(pf, Wk3, FDIM, (ci + 1) * 64, tid);
        else        prefetch_w(pf, Wv1, 64, 0, tid);
        gemm_tile_t<false, false>(bufA, Wst, nullptr, acc);

        if (ci == 0) {
#pragma unroll
            for (int k = 0; k < 4; k++) {
                const int t = j0 + 2 * k;
                float4 wla = *reinterpret_cast<const float4*>(WLs + t * 4);
                float4 wlb = *reinterpret_cast<const float4*>(WLs + t * 4 + 4);
                float qt0 = qrow[t], qt1 = qrow[t + 1];
                float4 xv0 = *reinterpret_cast<const float4*>(xs + t * 64 + exs);
                float4 xv1 = *reinterpret_cast<const float4*>(xs + (t + 1) * 64 + exs);
                float x0a[4] = {xv0.x, xv0.y, xv0.z, xv0.w};
                float x1a[4] = {xv1.x, xv1.y, xv1.z, xv1.w};
#pragma unroll
                for (int i = 0; i < 4; i++) {
                    float2 v = unpack2(acc[i][k]);
                    float c0 = qt0 * x0a[i] * v.x;
                    float c1 = qt1 * x1a[i] * v.y;
                    pl[i][0] += c0 * wla.x + c1 * wlb.x;
                    pl[i][1] += c0 * wla.y + c1 * wlb.y;
                    pl[i][2] += c0 * wla.z + c1 * wlb.z;
                    pl[i][3] += c0 * wla.w + c1 * wlb.w;
                }
            }
        } else {
            const int d = 8 * (ci - 1) + (tid & 7);
            const int exd = e0t ^ ((((ci - 1)) & 7) << 2);   // swz(d), d>>3 = ci-1
            float4 wl = *reinterpret_cast<const float4*>(WLs + (64 + d) * 4);
            float4 xv = *reinterpret_cast<const float4*>(xs + d * 64 + exd);
            float qd = qrow[d];
            float qx[4] = {qd * xv.x, qd * xv.y, qd * xv.z, qd * xv.w};
#pragma unroll
            for (int k = 0; k < 4; k++) {
                float4 sh0 = *reinterpret_cast<const float4*>(shm + (2 * k) * 64 + e0t);
                float4 sh1 = *reinterpret_cast<const float4*>(shm + (2 * k + 1) * 64 + e0t);
                float s0a[4] = {sh0.x * sh0.x, sh0.y * sh0.y, sh0.z * sh0.z, sh0.w * sh0.w};
                float s1a[4] = {sh1.x * sh1.x, sh1.y * sh1.y, sh1.z * sh1.z, sh1.w * sh1.w};
#pragma unroll
                for (int i = 0; i < 4; i++) {
                    float2 v = unpack2(acc[i][k]);
                    float cm = qx[i] * (s0a[i] * v.x + s1a[i] * v.y);
                    pl[i][0] += cm * wl.x;
                    pl[i][1] += cm * wl.y;
                    pl[i][2] += cm * wl.z;
                    pl[i][3] += cm * wl.w;
                }
            }
        }
        __syncthreads();
        commit_w(Wst, pf, tid);
        __syncthreads();
    }

    // logit reduction over the 8 column-lanes
#pragma unroll
    for (int m = 1; m < 8; m <<= 1)
#pragma unroll
        for (int i = 0; i < 4; i++)
#pragma unroll
            for (int h = 0; h < 4; h++)
                pl[i][h] += __shfl_xor_sync(0xffffffffu, pl[i][h], m);
    if ((tid & 7) == 0) {
#pragma unroll
        for (int i = 0; i < 4; i++)
            *reinterpret_cast<float4*>(lg + (e0t + i) * 4) =
                make_float4(pl[i][0], pl[i][1], pl[i][2], pl[i][3]);
    }

    // reload edge_inv (bufA's key h2 dead)
    for (int idx = tid; idx < 1024; idx += THREADS) {
        int e  = idx & 63;
        int c4 = (idx >> 6) << 2;
        float4 v = *reinterpret_cast<const float4*>(edge_inv + (eg0 + e) * 64 + c4);
        int ep = e ^ (((c4 >> 3) & 7) << 2);
        bufA[(c4 + 0) * 64 + ep] = v.x;
        bufA[(c4 + 1) * 64 + ep] = v.y;
        bufA[(c4 + 2) * 64 + ep] = v.z;
        bufA[(c4 + 3) * 64 + ep] = v.w;
    }
    __syncthreads();

    // ---------- softmax per (node, head) -> al transposed [h][e] ----------
    if (tid < GN * HHEAD) {
        int n = tid >> 2, h = tid & 3;
        float mx = -3.0e38f;
        for (int j = 0; j < KEDGE; j++)
            mx = fmaxf(mx, lg[(n * KEDGE + j) * 4 + h]);
        float z = 0.f;
        float ex[KEDGE];
        for (int j = 0; j < KEDGE; j++) {
            int e = n * KEDGE + j;
            ex[j] = cw[e] * expf(lg[e * 4 + h] - mx);
            z += ex[j];
        }
        if (z == 0.f) z = 1.f;
        float inv = 1.f / z;
        for (int j = 0; j < KEDGE; j++)
            al[h * 64 + n * KEDGE + j] = sqrtf(ex[j] * inv);
    }

    // ---------- value MLP layers 1,2 ----------
    prefetch_w(pf, Wv2, 64, 0, tid);
    gemm_tile_t<true, true>(bufA, Wst, bufB, acc);
    __syncthreads();
    commit_w(Wst, pf, tid);
    __syncthreads();

    prefetch_w(pf, Wv3, FDIM, 0, tid);
    gemm_tile_t<true, true>(bufB, Wst, bufA, acc);
    __syncthreads();
    commit_w(Wst, pf, tid);
    __syncthreads();

    float* accN = bufB;   // [4][576], fully written below

    // ---------- value chunks -> node accumulators ----------
    for (int ci = 0; ci < 9; ci++) {
        if (ci < 8) prefetch_w(pf, Wv3, FDIM, (ci + 1) * 64, tid);
        gemm_tile_t<false, false>(bufA, Wst, nullptr, acc);

        float pk0[4] = {0.f, 0.f, 0.f, 0.f};
        float pk1[4] = {0.f, 0.f, 0.f, 0.f};
        const int clo = ci * 64 + j0;

        if (ci == 0) {
            float4 alv = *reinterpret_cast<const float4*>(al + e0t);  // head 0
            float ala[4] = {alv.x, alv.y, alv.z, alv.w};
#pragma unroll
            for (int k = 0; k < 4; k++) {
                const int t = j0 + 2 * k;
                float4 xv0 = *reinterpret_cast<const float4*>(xs + t * 64 + exs);
                float4 xv1 = *reinterpret_cast<const float4*>(xs + (t + 1) * 64 + exs);
                float x0a[4] = {xv0.x, xv0.y, xv0.z, xv0.w};
                float x1a[4] = {xv1.x, xv1.y, xv1.z, xv1.w};
#pragma unroll
                for (int i = 0; i < 4; i++) {
                    float2 v = unpack2(acc[i][k]);
                    pk0[k] += x0a[i] * v.x * ala[i];
                    pk1[k] += x1a[i] * v.y * ala[i];
                }
            }
        } else {
            const int d = 8 * (ci - 1) + (tid & 7);
            const int exd = e0t ^ ((((ci - 1)) & 7) << 2);
            float4 xv = *reinterpret_cast<const float4*>(xs + d * 64 + exd);
            float xa[4] = {xv.x, xv.y, xv.z, xv.w};
            const int ha = clo / FPH;
            const int hb = (clo + 7) / FPH;
            const int thr = (ha + 1) * FPH;
            float4 aAv = *reinterpret_cast<const float4*>(al + ha * 64 + e0t);
            float4 aBv = *reinterpret_cast<const float4*>(al + hb * 64 + e0t);
            float aAa[4] = {aAv.x, aAv.y, aAv.z, aAv.w};
            float aBa[4] = {aBv.x, aBv.y, aBv.z, aBv.w};
#pragma unroll
            for (int k = 0; k < 4; k++) {
                float4 sh0 = *reinterpret_cast<const float4*>(shm + (2 * k) * 64 + e0t);
                float4 sh1 = *reinterpret_cast<const float4*>(shm + (2 * k + 1) * 64 + e0t);
                float s0a[4] = {sh0.x, sh0.y, sh0.z, sh0.w};
                float s1a[4] = {sh1.x, sh1.y, sh1.z, sh1.w};
                const bool b0 = (clo + 2 * k >= thr);
                const bool b1 = (clo + 2 * k + 1 >= thr);
#pragma unroll
                for (int i = 0; i < 4; i++) {
                    float2 v = unpack2(acc[i][k]);
                    float a0 = b0 ? aBa[i] : aAa[i];
                    float a1 = b1 ? aBa[i] : aAa[i];
                    pk0[k] += xa[i] * s0a[i] * v.x * a0;
                    pk1[k] += xa[i] * s1a[i] * v.y * a1;
                }
            }
        }
        // reduce over the 4 edge-groups (lane bits 3,4)
#pragma unroll
        for (int k = 0; k < 4; k++) {
            pk0[k] += __shfl_xor_sync(0xffffffffu, pk0[k], 8);
            pk0[k] += __shfl_xor_sync(0xffffffffu, pk0[k], 16);
            pk1[k] += __shfl_xor_sync(0xffffffffu, pk1[k], 8);
            pk1[k] += __shfl_xor_sync(0xffffffffu, pk1[k], 16);
        }
        if ((tid & 31) < 8) {
#pragma unroll
            for (int k = 0; k < 4; k++)
                *reinterpret_cast<float2*>(accN + nt * FDIM + clo + 2 * k) =
                    make_float2(pk0[k], pk1[k]);
        }
        __syncthreads();
        if (ci < 8) {
            commit_w(Wst, pf, tid);
            __syncthreads();
        }
    }

    // ---------- epilogue: out[n] = accN[n] @ W_out, c-split across halves ----------
    {
        const int dcol = tid & 63;
        const int half = tid >> 6;
        const int cbeg = half * 288;
        float s[4] = {0.f, 0.f, 0.f, 0.f};
        for (int c = cbeg; c < cbeg + 288; c += 4) {
            float4 a0 = *reinterpret_cast<const float4*>(accN + 0 * FDIM + c);
            float4 a1 = *reinterpret_cast<const float4*>(accN + 1 * FDIM + c);
            float4 a2 = *reinterpret_cast<const float4*>(accN + 2 * FDIM + c);
            float4 a3 = *reinterpret_cast<const float4*>(accN + 3 * FDIM + c);
            float w0 = W_out[(c + 0) * 64 + dcol];
            float w1 = W_out[(c + 1) * 64 + dcol];
            float w2 = W_out[(c + 2) * 64 + dcol];
            float w3 = W_out[(c + 3) * 64 + dcol];
            s[0] += a0.x * w0 + a0.y * w1 + a0.z * w2 + a0.w * w3;
            s[1] += a1.x * w0 + a1.y * w1 + a1.z * w2 + a1.w * w3;
            s[2] += a2.x * w0 + a2.y * w1 + a2.z * w2 + a2.w * w3;
            s[3] += a3.x * w0 + a3.y * w1 + a3.z * w2 + a3.w * w3;
        }
        if (half == 1) {
#pragma unroll
            for (int n = 0; n < 4; n++) Wst[n * 64 + dcol] = s[n];
        }
        __syncthreads();
        if (half == 0) {
#pragma unroll
            for (int n = 0; n < 4; n++)
                out[(n0 + n) * 64 + dcol] = s[n] + Wst[n * 64 + dcol];
        }
    }
}

extern "C" void kernel_launch(void* const* d_in, const int* in_sizes, int n_in,
                              void* d_out, int out_size) {
    const float* node_feat = (const float*)d_in[0];
    const float* edge_sh   = (const float*)d_in[1];
    const float* edge_inv  = (const float*)d_in[2];
    const float* cutoff    = (const float*)d_in[3];
    const float* Wk1       = (const float*)d_in[4];
    const float* Wk2       = (const float*)d_in[5];
    const float* Wk3       = (const float*)d_in[6];
    const float* Wv1       = (const float*)d_in[7];
    const float* Wv2       = (const float*)d_in[8];
    const float* Wv3       = (const float*)d_in[9];
    const float* W_logit   = (const float*)d_in[10];
    const float* W_out     = (const float*)d_in[11];
    const int*   edge_src  = (const int*)d_in[12];
    float* out = (float*)d_out;

    size_t smem = SMEM_FLOATS * sizeof(float);
    cudaFuncSetAttribute(fused_attn_kernel,
                         cudaFuncAttributeMaxDynamicSharedMemorySize, (int)smem);
    fused_attn_kernel<<<NNODES / GN, THREADS, smem>>>(
        node_feat, edge_sh, edge_inv, cutoff,
        Wk1, Wk2, Wk3, Wv1, Wv2, Wv3,
        W_logit, W_out, edge_src, out);
}